// round 13
// baseline (speedup 1.0000x reference)
#include <cuda_runtime.h>
#include <cuda_fp16.h>
#include <math.h>
#include <float.h>

#define N_NODES 50000
#define MAX_E   800000
#define IN_C    96
#define HID_C   64
#define OUT_C   40

// ---------------- scratch (no allocations allowed) ----------------
// g_cnt invariant: zero at every kernel_launch entry (.bss zero at load;
// re-zeroed inside k_scan23_fill on every invocation).
__device__ int    g_is64;
__device__ int    g_cnt[N_NODES];
__device__ int    g_rowptr[N_NODES + 1];
__device__ int    g_fill[N_NODES];
__device__ int2   g_edge[MAX_E];             // {src, weight-as-int-bits}
__device__ float  g_dinv[N_NODES];
__device__ float  g_dinv2[N_NODES];
__device__ int    g_bsum[64];
__device__ unsigned int g_bar;               // monotonic grid-barrier ticket
__device__ __align__(128) __half g_hb[3][N_NODES * HID_C];   // 64-ch fp16
__device__ __align__(128) __half g_h40[2][N_NODES * OUT_C];  // 40-ch fp16

// ---- launch 0: GEMM0 (16 nodes/block) + edge degree count + dtype detect --
__global__ void k_gemm0(const float* __restrict__ x, const float* __restrict__ W0,
                        const void* __restrict__ ei, int E) {
    __shared__ float sWt[IN_C * HID_C];   // [k][c] = W0[c*96+k], 24 KB
    __shared__ float sx[16 * IN_C];       // 6 KB
    __shared__ int   s_is64;
    int tid = threadIdx.x;                // 256 threads
    int node0 = blockIdx.x * 16;

    if (tid == 0) {
        // Sample within first E/2 long longs (= E int32s): in-bounds either way.
        // int64 data: all sampled values in [0, N). int32 viewed as int64: hi
        // word almost surely nonzero -> out of range.
        const long long* p64 = (const long long*)ei;
        int ok = 1;
        int step = (E / 2) / 16;
        for (int k = 0; k < 16; k++) {
            long long v = p64[(size_t)k * step];
            if (v < 0 || v >= N_NODES) ok = 0;
        }
        s_is64 = ok;
        if (blockIdx.x == 0) g_is64 = ok;   // for later kernels
    }
    for (int i = tid; i < IN_C * HID_C; i += 256) {
        int k = i >> 6, c = i & 63;
        sWt[i] = W0[c * IN_C + k];
    }
    for (int i = tid; i < 16 * IN_C; i += 256) {
        int r = i / IN_C, k = i % IN_C;
        int node = node0 + r;
        sx[i] = (node < N_NODES) ? x[node * IN_C + k] : 0.0f;
    }
    __syncthreads();

    // fused degree count: grid covers E edges exactly (3125*256 = 800000)
    int is64 = s_is64;
    for (int e = blockIdx.x * 256 + tid; e < E; e += gridDim.x * 256) {
        int d;
        if (is64) d = (int)((const long long*)ei)[(size_t)E + e];
        else      d = ((const int*)ei)[E + e];
        atomicAdd(&g_cnt[d], 1);
    }

    int r4 = tid >> 6, c = tid & 63;
    float acc0 = 0.f, acc1 = 0.f, acc2 = 0.f, acc3 = 0.f;
#pragma unroll
    for (int k = 0; k < IN_C; k++) {
        float w = sWt[k * HID_C + c];
        acc0 += sx[(r4 + 0) * IN_C + k] * w;
        acc1 += sx[(r4 + 4) * IN_C + k] * w;
        acc2 += sx[(r4 + 8) * IN_C + k] * w;
        acc3 += sx[(r4 + 12) * IN_C + k] * w;
    }
    int n0 = node0 + r4;
    if (n0 < N_NODES)      g_hb[0][(n0) * HID_C + c]      = __float2half_rn(acc0);
    if (n0 + 4 < N_NODES)  g_hb[0][(n0 + 4) * HID_C + c]  = __float2half_rn(acc1);
    if (n0 + 8 < N_NODES)  g_hb[0][(n0 + 8) * HID_C + c]  = __float2half_rn(acc2);
    if (n0 + 12 < N_NODES) g_hb[0][(n0 + 12) * HID_C + c] = __float2half_rn(acc3);
}

// ---- launch 1: scan pass 1 (block sums) + dinv ----
#define SCAN_CHUNK 1024
#define SCAN_NBLK  ((N_NODES + SCAN_CHUNK - 1) / SCAN_CHUNK)   // 49

__global__ void k_scan1() {
    __shared__ int sh[SCAN_CHUNK];
    int t = threadIdx.x;
    int idx = blockIdx.x * SCAN_CHUNK + t;
    int c = (idx < N_NODES) ? g_cnt[idx] : 0;
    if (idx < N_NODES) {
        float deg = (float)(c + 1);   // +1 self loop
        g_dinv[idx]  = rsqrtf(deg);
        g_dinv2[idx] = 1.0f / deg;    // self-loop norm = dinv^2
    }
    sh[t] = c;
    __syncthreads();
    for (int off = SCAN_CHUNK >> 1; off > 0; off >>= 1) {
        if (t < off) sh[t] += sh[t + off];
        __syncthreads();
    }
    if (t == 0) g_bsum[blockIdx.x] = sh[0];
}

// ---- launch 2: rowptr scan + re-zero g_cnt + grid barrier + CSR fill ----
// 49 blocks of 1024 threads: all co-resident on 148 SMs -> software grid
// barrier is safe. Monotonic ticket counter works across graph replays
// without reset (every invocation adds exactly SCAN_NBLK arrivals).
__global__ void k_scan23_fill(const void* __restrict__ ei, int E) {
    __shared__ int sh[SCAN_CHUNK];
    __shared__ int bsm[64];
    __shared__ int base_sh;
    int t = threadIdx.x;
    int idx = blockIdx.x * SCAN_CHUNK + t;
    int v = (idx < N_NODES) ? g_cnt[idx] : 0;
    if (idx < N_NODES) g_cnt[idx] = 0;       // restore invariant for next call
    sh[t] = v;
    if (t < 64) bsm[t] = (t < blockIdx.x && t < SCAN_NBLK) ? g_bsum[t] : 0;
    __syncthreads();
    for (int off = 1; off < SCAN_CHUNK; off <<= 1) {   // inclusive scan
        int x = (t >= off) ? sh[t - off] : 0;
        __syncthreads();
        sh[t] += x;
        __syncthreads();
    }
    if (t < 32) {
        int s = bsm[t] + bsm[t + 32];
#pragma unroll
        for (int off = 16; off > 0; off >>= 1)
            s += __shfl_xor_sync(0xffffffffu, s, off);
        if (t == 0) base_sh = s;
    }
    __syncthreads();
    int base = base_sh;
    if (idx < N_NODES) {
        int ex = base + sh[t] - v;
        g_rowptr[idx] = ex;
        g_fill[idx]   = ex;
        if (idx == N_NODES - 1) g_rowptr[N_NODES] = base + sh[t];
    }

    // ---- grid barrier ----
    __threadfence();
    __syncthreads();
    if (t == 0) {
        unsigned int ticket = atomicAdd(&g_bar, 1u);
        unsigned int target = (ticket / SCAN_NBLK + 1u) * SCAN_NBLK;
        while (*(volatile unsigned int*)&g_bar < target) { }
    }
    __syncthreads();
    __threadfence();

    // ---- CSR fill (grid-stride over edges) ----
    int is64 = g_is64;
    int nthr = gridDim.x * SCAN_CHUNK;
    for (int e = blockIdx.x * SCAN_CHUNK + t; e < E; e += nthr) {
        int s, d;
        if (is64) {
            const long long* p = (const long long*)ei;
            s = (int)p[e];
            d = (int)p[(size_t)E + e];
        } else {
            const int* p = (const int*)ei;
            s = p[e];
            d = p[E + e];
        }
        int pos = atomicAdd(&g_fill[d], 1);
        g_edge[pos] = make_int2(s, __float_as_int(g_dinv[s] * g_dinv[d]));
    }
}

// ---------------- GEMM 2: Y = H @ W4^T  (N x 64 fp16 -> N x 40 fp16) ------
__global__ void k_gemm4(const float* __restrict__ W4, int in_i) {
    __shared__ float sWt[HID_C * OUT_C];   // 10 KB
    __shared__ float sh[8 * HID_C];
    const __half* __restrict__ hin = g_hb[in_i];
    int tid = threadIdx.x;                 // 320 threads
    int node0 = blockIdx.x * 8;
    for (int i = tid; i < HID_C * OUT_C; i += 320) {
        int k = i / OUT_C, c = i % OUT_C;
        sWt[i] = W4[c * HID_C + k];
    }
    for (int i = tid; i < 8 * HID_C; i += 320) {
        int r = i >> 6, k = i & 63;
        int node = node0 + r;
        sh[i] = (node < N_NODES) ? __half2float(hin[node * HID_C + k]) : 0.0f;
    }
    __syncthreads();
    int r = tid / OUT_C, c = tid % OUT_C;
    int node = node0 + r;
    if (node >= N_NODES) return;
    float acc = 0.0f;
#pragma unroll
    for (int k = 0; k < HID_C; k++)
        acc += sh[r * HID_C + k] * sWt[k * OUT_C + c];
    g_h40[0][node * OUT_C + c] = __float2half_rn(acc);
}

// ---------------- prop, 64 channels fp16, one warp per node ----------------
// mode 0: out = S h          mode 1: out = S h + bias
// mode 2: out = 0.8 S h + 0.2 h0   mode 3: leaky_relu(mode 2)
__global__ void k_prop64(int in_i, int h0_i, const float* __restrict__ bias,
                         int out_i, int mode) {
    int gw = (blockIdx.x * blockDim.x + threadIdx.x) >> 5;
    int lane = threadIdx.x & 31;
    if (gw >= N_NODES) return;
    const __half2* __restrict__ h2 = (const __half2*)g_hb[in_i];
    int r0 = g_rowptr[gw], r1 = g_rowptr[gw + 1];
    float dl = g_dinv2[gw];
    float2 hv = __half22float2(h2[gw * 32 + lane]);
    float ax = dl * hv.x, ay = dl * hv.y;

    int deg = r1 - r0;
    int e = r0 + lane;
#pragma unroll 1
    while (deg > 0) {
        int2 ed = make_int2(0, 0);
        if (lane < deg) ed = g_edge[e];
        int cnt = min(deg, 32);
        int jb = 0;
#pragma unroll 1
        for (; jb + 8 <= cnt; jb += 8) {
            __half2 v[8];
            float w[8];
#pragma unroll
            for (int j = 0; j < 8; j++) {
                int   s = __shfl_sync(0xffffffffu, ed.x, jb + j);
                w[j]    = __int_as_float(__shfl_sync(0xffffffffu, ed.y, jb + j));
                v[j]    = h2[s * 32 + lane];
            }
#pragma unroll
            for (int j = 0; j < 8; j++) {
                float2 f = __half22float2(v[j]);
                ax += w[j] * f.x;
                ay += w[j] * f.y;
            }
        }
#pragma unroll 1
        for (; jb < cnt; jb++) {
            int   s = __shfl_sync(0xffffffffu, ed.x, jb);
            float w = __int_as_float(__shfl_sync(0xffffffffu, ed.y, jb));
            float2 f = __half22float2(h2[s * 32 + lane]);
            ax += w * f.x;
            ay += w * f.y;
        }
        deg -= 32;
        e += 32;
    }

    int o = gw * 32 + lane;
    float2 r;
    if (mode == 0) {
        r.x = ax; r.y = ay;
    } else if (mode == 1) {
        r.x = ax + bias[2 * lane];
        r.y = ay + bias[2 * lane + 1];
    } else {
        const __half2* __restrict__ h02 = (const __half2*)g_hb[h0_i];
        float2 z = __half22float2(h02[o]);
        r.x = 0.8f * ax + 0.2f * z.x;
        r.y = 0.8f * ay + 0.2f * z.y;
        if (mode == 3) {
            r.x = (r.x > 0.0f) ? r.x : 0.01f * r.x;
            r.y = (r.y > 0.0f) ? r.y : 0.01f * r.y;
        }
    }
    ((__half2*)g_hb[out_i])[o] = __float22half2_rn(r);
}

// ---------------- prop, 40 channels fp16 ----------------
__global__ void k_prop40(const float* __restrict__ b4, float* __restrict__ dout,
                         int mode) {
    int gw = (blockIdx.x * blockDim.x + threadIdx.x) >> 5;
    int lane = threadIdx.x & 31;
    if (gw >= N_NODES) return;
    const __half2* __restrict__ h2 = (const __half2*)g_h40[mode ? 1 : 0];
    int r0 = g_rowptr[gw], r1 = g_rowptr[gw + 1];
    bool act = (lane < 20);
    float dl = g_dinv2[gw];
    float a0 = 0.0f, a1 = 0.0f;
    if (act) {
        float2 hv = __half22float2(h2[gw * 20 + lane]);
        a0 = dl * hv.x;
        a1 = dl * hv.y;
    }
    int deg = r1 - r0;
    int e = r0 + lane;
#pragma unroll 1
    while (deg > 0) {
        int2 ed = make_int2(0, 0);
        if (lane < deg) ed = g_edge[e];
        int cnt = min(deg, 32);
#pragma unroll 1
        for (int jb = 0; jb < cnt; jb++) {
            int s = __shfl_sync(0xffffffffu, ed.x, jb);
            float w = __int_as_float(__shfl_sync(0xffffffffu, ed.y, jb));
            if (act) {
                float2 f = __half22float2(h2[s * 20 + lane]);
                a0 += w * f.x;
                a1 += w * f.y;
            }
        }
        deg -= 32;
        e += 32;
    }
    if (mode == 0) {
        if (act) {
            float2 r; r.x = a0; r.y = a1;
            ((__half2*)g_h40[1])[gw * 20 + lane] = __float22half2_rn(r);
        }
    } else {
        float v0 = act ? (a0 + b4[2 * lane])     : -FLT_MAX;
        float v1 = act ? (a1 + b4[2 * lane + 1]) : -FLT_MAX;
        float mx = fmaxf(v0, v1);
#pragma unroll
        for (int off = 16; off > 0; off >>= 1)
            mx = fmaxf(mx, __shfl_xor_sync(0xffffffffu, mx, off));
        float se = act ? (expf(v0 - mx) + expf(v1 - mx)) : 0.0f;
#pragma unroll
        for (int off = 16; off > 0; off >>= 1)
            se += __shfl_xor_sync(0xffffffffu, se, off);
        float l = mx + logf(se);
        if (act) {
            dout[gw * OUT_C + 2 * lane]     = v0 - l;
            dout[gw * OUT_C + 2 * lane + 1] = v1 - l;
        }
    }
}

// ---------------- launch ----------------
extern "C" void kernel_launch(void* const* d_in, const int* in_sizes, int n_in,
                              void* d_out, int out_size) {
    const float* x  = (const float*)d_in[0];
    const void*  ei = d_in[1];
    const float* W0 = (const float*)d_in[2];
    const float* b0 = (const float*)d_in[3];
    const float* W4 = (const float*)d_in[4];
    const float* b4 = (const float*)d_in[5];
    float* out = (float*)d_out;
    int E = in_sizes[1] / 2;

    int nb_w = (N_NODES * 32 + 255) / 256;   // one warp per node

    // launches 0-2: GEMM0 (+count+detect), scan1, scan23+fill
    k_gemm0<<<(N_NODES + 15) / 16, 256>>>(x, W0, ei, E);
    k_scan1<<<SCAN_NBLK, SCAN_CHUNK>>>();
    k_scan23_fill<<<SCAN_NBLK, SCAN_CHUNK>>>(ei, E);

    // launch 3 onward: propagation (ncu profiles launch #3 = first prop64)
    // conv0 (SGConv): hb0 = S^2(x W0^T) + b0
    k_prop64<<<nb_w, 256>>>(0, 0, b0, 1, 0);              // hb1 = S hb0
    k_prop64<<<nb_w, 256>>>(1, 0, b0, 0, 1);              // hb0 = S hb1 + b0
    // conv1 APPNP + lrelu (h0 = hb0)
    k_prop64<<<nb_w, 256>>>(0, 0, b0, 1, 2);              // hb1
    k_prop64<<<nb_w, 256>>>(1, 0, b0, 2, 3);              // hb2
    // conv2 (h0 = hb2)
    k_prop64<<<nb_w, 256>>>(2, 2, b0, 0, 2);              // hb0
    k_prop64<<<nb_w, 256>>>(0, 2, b0, 1, 3);              // hb1
    // conv3 (h0 = hb1)
    k_prop64<<<nb_w, 256>>>(1, 1, b0, 0, 2);              // hb0
    k_prop64<<<nb_w, 256>>>(0, 1, b0, 2, 3);              // hb2

    // conv4 (SGConv): out = log_softmax(S^2(hb2 W4^T) + b4)
    k_gemm4<<<(N_NODES + 7) / 8, 320>>>(W4, 2);           // h40[0]
    k_prop40<<<nb_w, 256>>>(b4, out, 0);                  // h40[1] = S h40[0]
    k_prop40<<<nb_w, 256>>>(b4, out, 1);                  // out
}

// round 14
// speedup vs baseline: 1.2603x; 1.2603x over previous
#include <cuda_runtime.h>
#include <cuda_fp16.h>
#include <math.h>
#include <float.h>

#define N_NODES 50000
#define MAX_E   800000
#define IN_C    96
#define HID_C   64
#define OUT_C   40

// ---------------- scratch (no allocations allowed) ----------------
// g_cnt invariant: zero at every kernel_launch entry (.bss zero at load;
// re-zeroed inside k_scan23_fill on every invocation).
__device__ int    g_is64;
__device__ int    g_cnt[N_NODES];
__device__ int    g_rowptr[N_NODES + 1];
__device__ int    g_fill[N_NODES];
__device__ int2   g_edge[MAX_E];             // {src, weight-as-int-bits}
__device__ float  g_dinv[N_NODES];
__device__ float  g_dinv2[N_NODES];
__device__ int    g_bsum[64];
__device__ unsigned int g_bar;               // monotonic grid-barrier ticket
__device__ __align__(128) __half g_hb[3][N_NODES * HID_C];   // 64-ch fp16
__device__ __align__(128) __half g_h40[2][N_NODES * OUT_C];  // 40-ch fp16

__device__ __forceinline__ float2 u2f(unsigned u) {
    __half2 h = *reinterpret_cast<__half2*>(&u);
    return __half22float2(h);
}

// ---- launch 0: GEMM0 (16 nodes/block) + edge degree count + dtype detect --
__global__ void k_gemm0(const float* __restrict__ x, const float* __restrict__ W0,
                        const void* __restrict__ ei, int E) {
    __shared__ float sWt[IN_C * HID_C];   // [k][c] = W0[c*96+k], 24 KB
    __shared__ float sx[16 * IN_C];       // 6 KB
    __shared__ int   s_is64;
    int tid = threadIdx.x;                // 256 threads
    int node0 = blockIdx.x * 16;

    if (tid == 0) {
        // Sample within first E/2 long longs (= E int32s): in-bounds either way.
        const long long* p64 = (const long long*)ei;
        int ok = 1;
        int step = (E / 2) / 16;
        for (int k = 0; k < 16; k++) {
            long long v = p64[(size_t)k * step];
            if (v < 0 || v >= N_NODES) ok = 0;
        }
        s_is64 = ok;
        if (blockIdx.x == 0) g_is64 = ok;
    }
    for (int i = tid; i < IN_C * HID_C; i += 256) {
        int k = i >> 6, c = i & 63;
        sWt[i] = W0[c * IN_C + k];
    }
    for (int i = tid; i < 16 * IN_C; i += 256) {
        int r = i / IN_C, k = i % IN_C;
        int node = node0 + r;
        sx[i] = (node < N_NODES) ? x[node * IN_C + k] : 0.0f;
    }
    __syncthreads();

    // fused degree count (grid covers E exactly: 3125*256 = 800000)
    int is64 = s_is64;
    for (int e = blockIdx.x * 256 + tid; e < E; e += gridDim.x * 256) {
        int d;
        if (is64) d = (int)((const long long*)ei)[(size_t)E + e];
        else      d = ((const int*)ei)[E + e];
        atomicAdd(&g_cnt[d], 1);
    }

    int r4 = tid >> 6, c = tid & 63;
    float acc0 = 0.f, acc1 = 0.f, acc2 = 0.f, acc3 = 0.f;
#pragma unroll
    for (int k = 0; k < IN_C; k++) {
        float w = sWt[k * HID_C + c];
        acc0 += sx[(r4 + 0) * IN_C + k] * w;
        acc1 += sx[(r4 + 4) * IN_C + k] * w;
        acc2 += sx[(r4 + 8) * IN_C + k] * w;
        acc3 += sx[(r4 + 12) * IN_C + k] * w;
    }
    int n0 = node0 + r4;
    if (n0 < N_NODES)      g_hb[0][(n0) * HID_C + c]      = __float2half_rn(acc0);
    if (n0 + 4 < N_NODES)  g_hb[0][(n0 + 4) * HID_C + c]  = __float2half_rn(acc1);
    if (n0 + 8 < N_NODES)  g_hb[0][(n0 + 8) * HID_C + c]  = __float2half_rn(acc2);
    if (n0 + 12 < N_NODES) g_hb[0][(n0 + 12) * HID_C + c] = __float2half_rn(acc3);
}

// ---- launch 1: scan pass 1 (block sums) + dinv ----
#define SCAN_CHUNK 1024
#define SCAN_NBLK  ((N_NODES + SCAN_CHUNK - 1) / SCAN_CHUNK)   // 49

__global__ void k_scan1() {
    __shared__ int sh[SCAN_CHUNK];
    int t = threadIdx.x;
    int idx = blockIdx.x * SCAN_CHUNK + t;
    int c = (idx < N_NODES) ? g_cnt[idx] : 0;
    if (idx < N_NODES) {
        float deg = (float)(c + 1);   // +1 self loop
        g_dinv[idx]  = rsqrtf(deg);
        g_dinv2[idx] = 1.0f / deg;    // self-loop norm = dinv^2
    }
    sh[t] = c;
    __syncthreads();
    for (int off = SCAN_CHUNK >> 1; off > 0; off >>= 1) {
        if (t < off) sh[t] += sh[t + off];
        __syncthreads();
    }
    if (t == 0) g_bsum[blockIdx.x] = sh[0];
}

// ---- launch 2: rowptr scan + re-zero g_cnt + grid barrier + CSR fill ----
__global__ void k_scan23_fill(const void* __restrict__ ei, int E) {
    __shared__ int sh[SCAN_CHUNK];
    __shared__ int bsm[64];
    __shared__ int base_sh;
    int t = threadIdx.x;
    int idx = blockIdx.x * SCAN_CHUNK + t;
    int v = (idx < N_NODES) ? g_cnt[idx] : 0;
    if (idx < N_NODES) g_cnt[idx] = 0;       // restore invariant for next call
    sh[t] = v;
    if (t < 64) bsm[t] = (t < blockIdx.x && t < SCAN_NBLK) ? g_bsum[t] : 0;
    __syncthreads();
    for (int off = 1; off < SCAN_CHUNK; off <<= 1) {   // inclusive scan
        int x = (t >= off) ? sh[t - off] : 0;
        __syncthreads();
        sh[t] += x;
        __syncthreads();
    }
    if (t < 32) {
        int s = bsm[t] + bsm[t + 32];
#pragma unroll
        for (int off = 16; off > 0; off >>= 1)
            s += __shfl_xor_sync(0xffffffffu, s, off);
        if (t == 0) base_sh = s;
    }
    __syncthreads();
    int base = base_sh;
    if (idx < N_NODES) {
        int ex = base + sh[t] - v;
        g_rowptr[idx] = ex;
        g_fill[idx]   = ex;
        if (idx == N_NODES - 1) g_rowptr[N_NODES] = base + sh[t];
    }

    // ---- grid barrier (49 co-resident blocks; monotonic ticket) ----
    __threadfence();
    __syncthreads();
    if (t == 0) {
        unsigned int ticket = atomicAdd(&g_bar, 1u);
        unsigned int target = (ticket / SCAN_NBLK + 1u) * SCAN_NBLK;
        while (*(volatile unsigned int*)&g_bar < target) { }
    }
    __syncthreads();
    __threadfence();

    // ---- CSR fill (grid-stride over edges) ----
    int is64 = g_is64;
    int nthr = gridDim.x * SCAN_CHUNK;
    for (int e = blockIdx.x * SCAN_CHUNK + t; e < E; e += nthr) {
        int s, d;
        if (is64) {
            const long long* p = (const long long*)ei;
            s = (int)p[e];
            d = (int)p[(size_t)E + e];
        } else {
            const int* p = (const int*)ei;
            s = p[e];
            d = p[E + e];
        }
        int pos = atomicAdd(&g_fill[d], 1);
        g_edge[pos] = make_int2(s, __float_as_int(g_dinv[s] * g_dinv[d]));
    }
}

// ---------------- GEMM 2: Y = H @ W4^T  (N x 64 fp16 -> N x 40 fp16) ------
__global__ void k_gemm4(const float* __restrict__ W4, int in_i) {
    __shared__ float sWt[HID_C * OUT_C];   // 10 KB
    __shared__ float sh[8 * HID_C];
    const __half* __restrict__ hin = g_hb[in_i];
    int tid = threadIdx.x;                 // 320 threads
    int node0 = blockIdx.x * 8;
    for (int i = tid; i < HID_C * OUT_C; i += 320) {
        int k = i / OUT_C, c = i % OUT_C;
        sWt[i] = W4[c * HID_C + k];
    }
    for (int i = tid; i < 8 * HID_C; i += 320) {
        int r = i >> 6, k = i & 63;
        int node = node0 + r;
        sh[i] = (node < N_NODES) ? __half2float(hin[node * HID_C + k]) : 0.0f;
    }
    __syncthreads();
    int r = tid / OUT_C, c = tid % OUT_C;
    int node = node0 + r;
    if (node >= N_NODES) return;
    float acc = 0.0f;
#pragma unroll
    for (int k = 0; k < HID_C; k++)
        acc += sh[r * HID_C + k] * sWt[k * OUT_C + c];
    g_h40[0][node * OUT_C + c] = __float2half_rn(acc);
}

// ---------------- prop, 64 channels fp16 ----------------
// TWO nodes per warp: half-warp per node, 16 lanes x half4 (uint2) per lane.
// Edge metadata: broadcast __ldg per half-warp (no shuffles).
// mode 0: out = S h          mode 1: out = S h + bias
// mode 2: out = 0.8 S h + 0.2 h0   mode 3: leaky_relu(mode 2)
__global__ void k_prop64(int in_i, int h0_i, const float* __restrict__ bias,
                         int out_i, int mode) {
    int gw = (blockIdx.x * blockDim.x + threadIdx.x) >> 5;
    int lane = threadIdx.x & 31;
    int side = lane >> 4;
    int l16  = lane & 15;
    int node = gw * 2 + side;
    if (node >= N_NODES) return;
    const uint2* __restrict__ hin2 = (const uint2*)g_hb[in_i];

    int r0 = __ldg(&g_rowptr[node]);
    int r1 = __ldg(&g_rowptr[node + 1]);
    float dl = __ldg(&g_dinv2[node]);

    // self loop: this lane's 4 channels
    uint2 us = __ldg(&hin2[node * 16 + l16]);
    float2 f01 = u2f(us.x), f23 = u2f(us.y);
    float a0 = dl * f01.x, a1 = dl * f01.y, a2 = dl * f23.x, a3 = dl * f23.y;

    int e = r0, deg = r1 - r0;
#pragma unroll 1
    while (deg >= 4) {
        int2 e0 = __ldg(&g_edge[e]);
        int2 e1 = __ldg(&g_edge[e + 1]);
        int2 e2 = __ldg(&g_edge[e + 2]);
        int2 e3 = __ldg(&g_edge[e + 3]);
        uint2 v0 = __ldg(&hin2[e0.x * 16 + l16]);
        uint2 v1 = __ldg(&hin2[e1.x * 16 + l16]);
        uint2 v2 = __ldg(&hin2[e2.x * 16 + l16]);
        uint2 v3 = __ldg(&hin2[e3.x * 16 + l16]);
        float w0 = __int_as_float(e0.y), w1 = __int_as_float(e1.y);
        float w2 = __int_as_float(e2.y), w3 = __int_as_float(e3.y);
        float2 p, q;
        p = u2f(v0.x); q = u2f(v0.y);
        a0 += w0 * p.x; a1 += w0 * p.y; a2 += w0 * q.x; a3 += w0 * q.y;
        p = u2f(v1.x); q = u2f(v1.y);
        a0 += w1 * p.x; a1 += w1 * p.y; a2 += w1 * q.x; a3 += w1 * q.y;
        p = u2f(v2.x); q = u2f(v2.y);
        a0 += w2 * p.x; a1 += w2 * p.y; a2 += w2 * q.x; a3 += w2 * q.y;
        p = u2f(v3.x); q = u2f(v3.y);
        a0 += w3 * p.x; a1 += w3 * p.y; a2 += w3 * q.x; a3 += w3 * q.y;
        e += 4; deg -= 4;
    }
#pragma unroll 1
    while (deg > 0) {
        int2 e0 = __ldg(&g_edge[e]);
        uint2 v0 = __ldg(&hin2[e0.x * 16 + l16]);
        float w0 = __int_as_float(e0.y);
        float2 p = u2f(v0.x), q = u2f(v0.y);
        a0 += w0 * p.x; a1 += w0 * p.y; a2 += w0 * q.x; a3 += w0 * q.y;
        e++; deg--;
    }

    float o0 = a0, o1 = a1, o2 = a2, o3 = a3;
    if (mode == 1) {
        float4 b = __ldg(&((const float4*)bias)[l16]);
        o0 += b.x; o1 += b.y; o2 += b.z; o3 += b.w;
    } else if (mode >= 2) {
        uint2 z = __ldg(&((const uint2*)g_hb[h0_i])[node * 16 + l16]);
        float2 z01 = u2f(z.x), z23 = u2f(z.y);
        o0 = 0.8f * a0 + 0.2f * z01.x;
        o1 = 0.8f * a1 + 0.2f * z01.y;
        o2 = 0.8f * a2 + 0.2f * z23.x;
        o3 = 0.8f * a3 + 0.2f * z23.y;
        if (mode == 3) {
            o0 = (o0 > 0.f) ? o0 : 0.01f * o0;
            o1 = (o1 > 0.f) ? o1 : 0.01f * o1;
            o2 = (o2 > 0.f) ? o2 : 0.01f * o2;
            o3 = (o3 > 0.f) ? o3 : 0.01f * o3;
        }
    }
    __half2 r01 = __floats2half2_rn(o0, o1);
    __half2 r23 = __floats2half2_rn(o2, o3);
    uint2 out;
    out.x = *reinterpret_cast<unsigned*>(&r01);
    out.y = *reinterpret_cast<unsigned*>(&r23);
    ((uint2*)g_hb[out_i])[node * 16 + l16] = out;
}

// ---------------- prop, 40 channels fp16 ----------------
// TWO nodes per warp: 16 lanes per node, lanes 0..9 active (10 x half4 = 40ch).
// mode 0: g_h40[0] -> g_h40[1]
// mode 1: g_h40[1] -> dout (fp32), + b4, half-warp log_softmax (fused)
__global__ void k_prop40(const float* __restrict__ b4, float* __restrict__ dout,
                         int mode) {
    int gw = (blockIdx.x * blockDim.x + threadIdx.x) >> 5;
    int lane = threadIdx.x & 31;
    int side = lane >> 4;
    int l16  = lane & 15;
    int node = gw * 2 + side;
    if (node >= N_NODES) return;
    const uint2* __restrict__ h2 = (const uint2*)g_h40[mode ? 1 : 0];
    bool act = (l16 < 10);

    int r0 = __ldg(&g_rowptr[node]);
    int r1 = __ldg(&g_rowptr[node + 1]);
    float dl = __ldg(&g_dinv2[node]);

    float a0 = 0.f, a1 = 0.f, a2 = 0.f, a3 = 0.f;
    if (act) {
        uint2 us = __ldg(&h2[node * 10 + l16]);
        float2 f01 = u2f(us.x), f23 = u2f(us.y);
        a0 = dl * f01.x; a1 = dl * f01.y; a2 = dl * f23.x; a3 = dl * f23.y;
    }
    int e = r0, deg = r1 - r0;
#pragma unroll 1
    while (deg >= 4) {
        int2 e0 = __ldg(&g_edge[e]);
        int2 e1 = __ldg(&g_edge[e + 1]);
        int2 e2 = __ldg(&g_edge[e + 2]);
        int2 e3 = __ldg(&g_edge[e + 3]);
        if (act) {
            uint2 v0 = __ldg(&h2[e0.x * 10 + l16]);
            uint2 v1 = __ldg(&h2[e1.x * 10 + l16]);
            uint2 v2 = __ldg(&h2[e2.x * 10 + l16]);
            uint2 v3 = __ldg(&h2[e3.x * 10 + l16]);
            float w0 = __int_as_float(e0.y), w1 = __int_as_float(e1.y);
            float w2 = __int_as_float(e2.y), w3 = __int_as_float(e3.y);
            float2 p, q;
            p = u2f(v0.x); q = u2f(v0.y);
            a0 += w0 * p.x; a1 += w0 * p.y; a2 += w0 * q.x; a3 += w0 * q.y;
            p = u2f(v1.x); q = u2f(v1.y);
            a0 += w1 * p.x; a1 += w1 * p.y; a2 += w1 * q.x; a3 += w1 * q.y;
            p = u2f(v2.x); q = u2f(v2.y);
            a0 += w2 * p.x; a1 += w2 * p.y; a2 += w2 * q.x; a3 += w2 * q.y;
            p = u2f(v3.x); q = u2f(v3.y);
            a0 += w3 * p.x; a1 += w3 * p.y; a2 += w3 * q.x; a3 += w3 * q.y;
        }
        e += 4; deg -= 4;
    }
#pragma unroll 1
    while (deg > 0) {
        int2 e0 = __ldg(&g_edge[e]);
        if (act) {
            uint2 v0 = __ldg(&h2[e0.x * 10 + l16]);
            float w0 = __int_as_float(e0.y);
            float2 p = u2f(v0.x), q = u2f(v0.y);
            a0 += w0 * p.x; a1 += w0 * p.y; a2 += w0 * q.x; a3 += w0 * q.y;
        }
        e++; deg--;
    }

    if (mode == 0) {
        if (act) {
            __half2 r01 = __floats2half2_rn(a0, a1);
            __half2 r23 = __floats2half2_rn(a2, a3);
            uint2 out;
            out.x = *reinterpret_cast<unsigned*>(&r01);
            out.y = *reinterpret_cast<unsigned*>(&r23);
            ((uint2*)g_h40[1])[node * 10 + l16] = out;
        }
    } else {
        float v0 = -FLT_MAX, v1 = -FLT_MAX, v2 = -FLT_MAX, v3 = -FLT_MAX;
        if (act) {
            float4 b = __ldg(&((const float4*)b4)[l16]);
            v0 = a0 + b.x; v1 = a1 + b.y; v2 = a2 + b.z; v3 = a3 + b.w;
        }
        float mx = fmaxf(fmaxf(v0, v1), fmaxf(v2, v3));
#pragma unroll
        for (int off = 8; off > 0; off >>= 1)   // stays within 16-lane group
            mx = fmaxf(mx, __shfl_xor_sync(0xffffffffu, mx, off));
        float se = act ? (expf(v0 - mx) + expf(v1 - mx) +
                          expf(v2 - mx) + expf(v3 - mx)) : 0.0f;
#pragma unroll
        for (int off = 8; off > 0; off >>= 1)
            se += __shfl_xor_sync(0xffffffffu, se, off);
        float l = mx + logf(se);
        if (act) {
            float4 o;
            o.x = v0 - l; o.y = v1 - l; o.z = v2 - l; o.w = v3 - l;
            ((float4*)dout)[node * 10 + l16] = o;
        }
    }
}

// ---------------- launch ----------------
extern "C" void kernel_launch(void* const* d_in, const int* in_sizes, int n_in,
                              void* d_out, int out_size) {
    const float* x  = (const float*)d_in[0];
    const void*  ei = d_in[1];
    const float* W0 = (const float*)d_in[2];
    const float* b0 = (const float*)d_in[3];
    const float* W4 = (const float*)d_in[4];
    const float* b4 = (const float*)d_in[5];
    float* out = (float*)d_out;
    int E = in_sizes[1] / 2;

    // 2 nodes per warp -> 25000 warps -> 800000 threads
    int nb_w = (N_NODES / 2 * 32 + 255) / 256;   // 3125 blocks

    // launches 0-2: GEMM0 (+count+detect), scan1, scan23+fill
    k_gemm0<<<(N_NODES + 15) / 16, 256>>>(x, W0, ei, E);
    k_scan1<<<SCAN_NBLK, SCAN_CHUNK>>>();
    k_scan23_fill<<<SCAN_NBLK, SCAN_CHUNK>>>(ei, E);

    // launch 3 onward: propagation (ncu profiles launch #3 = first prop64)
    // conv0 (SGConv): hb0 = S^2(x W0^T) + b0
    k_prop64<<<nb_w, 256>>>(0, 0, b0, 1, 0);              // hb1 = S hb0
    k_prop64<<<nb_w, 256>>>(1, 0, b0, 0, 1);              // hb0 = S hb1 + b0
    // conv1 APPNP + lrelu (h0 = hb0)
    k_prop64<<<nb_w, 256>>>(0, 0, b0, 1, 2);              // hb1
    k_prop64<<<nb_w, 256>>>(1, 0, b0, 2, 3);              // hb2
    // conv2 (h0 = hb2)
    k_prop64<<<nb_w, 256>>>(2, 2, b0, 0, 2);              // hb0
    k_prop64<<<nb_w, 256>>>(0, 2, b0, 1, 3);              // hb1
    // conv3 (h0 = hb1)
    k_prop64<<<nb_w, 256>>>(1, 1, b0, 0, 2);              // hb0
    k_prop64<<<nb_w, 256>>>(0, 1, b0, 2, 3);              // hb2

    // conv4 (SGConv): out = log_softmax(S^2(hb2 W4^T) + b4)
    k_gemm4<<<(N_NODES + 7) / 8, 320>>>(W4, 2);           // h40[0]
    k_prop40<<<nb_w, 256>>>(b4, out, 0);                  // h40[1] = S h40[0]
    k_prop40<<<nb_w, 256>>>(b4, out, 1);                  // out
}